// round 11
// baseline (speedup 1.0000x reference)
#include <cuda_runtime.h>

// ---------------------------------------------------------------------------
// SRR CG: out = relu(CG(AtA, b=At(slices), x0=volume, 10 iters))
// R11 = R9 structure (fused per-pixel AtA, 1 pixel/thread, grid=1024 -> 1.73
// waves so the scheduler rebalances the bimodal in/out-of-range rows; R10's
// one-wave pairing concentrated the imbalance and regressed 2x) plus:
//  - no k_fin launches: consumers redundantly finalize partial-sum arrays
//    per block (deterministic tree, L2-hot reads).
//  - b eliminated: At(slices) scatters straight into r.
// Scratch only via __device__ globals referenced INSIDE kernels.
// ---------------------------------------------------------------------------

#define NVOX (128*128*128)
#define NPIX (16*128*128)
#define TPB 256
#define NBLK 1024                 // blocks for 16MB elementwise passes
#define PIX_BLOCKS (NPIX / TPB)   // 1024 — pixel kernels, 1 px/thread

__device__ float g_x[NVOX];
__device__ float g_r[NVOX];
__device__ float g_p[NVOX];
__device__ float g_Ap[NVOX];
__device__ double g_part_pAp[PIX_BLOCKS];
__device__ double g_part_rr[2][NBLK];

// --------------------------- per-pixel frame -------------------------------

struct Frame {
    float R[9];
    float cx, cy, cz;
};

__device__ __forceinline__ Frame make_frame(int idx, const float* __restrict__ theta) {
    int w = idx & 127;
    int h = (idx >> 7) & 127;
    int n = idx >> 14;
    const float* T = theta + n * 12;
    Frame f;
    f.R[0] = T[0];  f.R[1] = T[1];  f.R[2] = T[2];
    f.R[3] = T[4];  f.R[4] = T[5];  f.R[5] = T[6];
    f.R[6] = T[8];  f.R[7] = T[9];  f.R[8] = T[10];
    float u = ((float)w - 63.5f) * 1.5f;
    float v = ((float)h - 63.5f) * 1.5f;
    f.cx = f.R[0]*u + f.R[1]*v + T[3]  + 63.5f;
    f.cy = f.R[3]*u + f.R[4]*v + T[7]  + 63.5f;
    f.cz = f.R[6]*u + f.R[7]*v + T[11] + 63.5f;
    return f;
}

// Center further than (sqrt(3) rotated PSF offset + 1 trilinear corner)
// outside [0,127] in any axis -> whole footprint out of bounds -> zero.
__device__ __forceinline__ bool in_range(const Frame& f) {
    return f.cx > -2.75f && f.cx < 129.75f &&
           f.cy > -2.75f && f.cy < 129.75f &&
           f.cz > -2.75f && f.cz < 129.75f;
}

// --------------------------- reductions ------------------------------------

__device__ __forceinline__ void block_reduce_store(double s, double* dst) {
    __shared__ double sm[TPB];
    sm[threadIdx.x] = s;
    __syncthreads();
    for (int off = TPB / 2; off > 0; off >>= 1) {
        if (threadIdx.x < off) sm[threadIdx.x] += sm[threadIdx.x + off];
        __syncthreads();
    }
    if (threadIdx.x == 0) dst[blockIdx.x] = sm[0];
}

// Reduce two values; every thread gets both sums (deterministic tree).
__device__ __forceinline__ void block_reduce2_all(double a, double b,
                                                  double& outa, double& outb) {
    __shared__ double smA[TPB], smB[TPB];
    smA[threadIdx.x] = a;
    smB[threadIdx.x] = b;
    __syncthreads();
    for (int off = TPB / 2; off > 0; off >>= 1) {
        if (threadIdx.x < off) {
            smA[threadIdx.x] += smA[threadIdx.x + off];
            smB[threadIdx.x] += smB[threadIdx.x + off];
        }
        __syncthreads();
    }
    outa = smA[0];
    outb = smB[0];
    __syncthreads();
}

// --------------------------- gather / scatter cores ------------------------

__device__ __forceinline__ float gather27(const Frame& f,
                                          const float* __restrict__ vol,
                                          const float* __restrict__ psf) {
    float acc = 0.f;
    int k = 0;
    #pragma unroll
    for (int a = -1; a <= 1; a++) {
        float oz = (float)a;
        #pragma unroll
        for (int b = -1; b <= 1; b++) {
            float oy = (float)b;
            #pragma unroll
            for (int c = -1; c <= 1; c++, k++) {
                float ox = (float)c;
                float px = f.cx + f.R[0]*ox + f.R[1]*oy + f.R[2]*oz;
                float py = f.cy + f.R[3]*ox + f.R[4]*oy + f.R[5]*oz;
                float pz = f.cz + f.R[6]*ox + f.R[7]*oy + f.R[8]*oz;
                float pk = __ldg(&psf[k]);
                float xf = floorf(px), yf = floorf(py), zf = floorf(pz);
                int x0 = (int)xf, y0 = (int)yf, z0 = (int)zf;
                float fx = px - xf, fy = py - yf, fz = pz - zf;
                float wx0 = 1.f - fx, wy0 = 1.f - fy, wz0 = 1.f - fz;
                float s = 0.f;
                #pragma unroll
                for (int dz = 0; dz < 2; dz++) {
                    float wz = dz ? fz : wz0;
                    int zi = z0 + dz;
                    #pragma unroll
                    for (int dy = 0; dy < 2; dy++) {
                        float wy = dy ? fy : wy0;
                        int yi = y0 + dy;
                        #pragma unroll
                        for (int dx = 0; dx < 2; dx++) {
                            float wx = dx ? fx : wx0;
                            int xi = x0 + dx;
                            if ((unsigned)xi < 128u && (unsigned)yi < 128u && (unsigned)zi < 128u)
                                s += wx * wy * wz * __ldg(&vol[(zi * 128 + yi) * 128 + xi]);
                        }
                    }
                }
                acc += pk * s;
            }
        }
    }
    return acc;
}

__device__ __forceinline__ void scatter27(const Frame& f, float* __restrict__ vol,
                                          const float* __restrict__ psf, float val) {
    int k = 0;
    #pragma unroll
    for (int a = -1; a <= 1; a++) {
        float oz = (float)a;
        #pragma unroll
        for (int b = -1; b <= 1; b++) {
            float oy = (float)b;
            #pragma unroll
            for (int c = -1; c <= 1; c++, k++) {
                float ox = (float)c;
                float px = f.cx + f.R[0]*ox + f.R[1]*oy + f.R[2]*oz;
                float py = f.cy + f.R[3]*ox + f.R[4]*oy + f.R[5]*oz;
                float pz = f.cz + f.R[6]*ox + f.R[7]*oy + f.R[8]*oz;
                float base = val * __ldg(&psf[k]);
                float xf = floorf(px), yf = floorf(py), zf = floorf(pz);
                int x0 = (int)xf, y0 = (int)yf, z0 = (int)zf;
                float fx = px - xf, fy = py - yf, fz = pz - zf;
                float wx0 = 1.f - fx, wy0 = 1.f - fy, wz0 = 1.f - fz;
                #pragma unroll
                for (int dz = 0; dz < 2; dz++) {
                    int zi = z0 + dz;
                    if ((unsigned)zi >= 128u) continue;
                    float bz = base * (dz ? fz : wz0);
                    #pragma unroll
                    for (int dy = 0; dy < 2; dy++) {
                        int yi = y0 + dy;
                        if ((unsigned)yi >= 128u) continue;
                        float byz = bz * (dy ? fy : wy0);
                        float* row = vol + (zi * 128 + yi) * 128;
                        if ((unsigned)x0 < 128u)       atomicAdd(row + x0,     byz * wx0);
                        if ((unsigned)(x0 + 1) < 128u) atomicAdd(row + x0 + 1, byz * fx);
                    }
                }
            }
        }
    }
}

// --------------------------- fused AtA kernel ------------------------------
// Per pixel: a = <w, src>;  dst += sign * a * w;  optional pAp partials (a^2).
// src_sel: 0 -> g_x, 1 -> g_p.   dst_sel: 1 -> g_r, 2 -> g_Ap.

__global__ void k_AtA(const float* __restrict__ theta, const float* __restrict__ psf,
                      int src_sel, int dst_sel, float sign, int do_dot) {
    const float* __restrict__ src = src_sel == 0 ? g_x : g_p;
    float* __restrict__ dst = dst_sel == 1 ? g_r : g_Ap;
    int idx = blockIdx.x * TPB + threadIdx.x;
    Frame f = make_frame(idx, theta);
    float acc = 0.f;
    bool inr = in_range(f);
    if (inr) {
        acc = gather27(f, src, psf);
        float val = sign * acc;
        if (val != 0.f)
            scatter27(f, dst, psf, val);
    }
    if (do_dot)
        block_reduce_store((double)acc * (double)acc, g_part_pAp);
}

// --------------------------- At (slices -> r) ------------------------------

__global__ void k_At_slices(const float* __restrict__ theta, const float* __restrict__ psf,
                            const float* __restrict__ slices) {
    int idx = blockIdx.x * TPB + threadIdx.x;
    Frame f = make_frame(idx, theta);
    if (!in_range(f)) return;
    float val = slices[idx];
    if (val != 0.f)
        scatter27(f, g_r, psf, val);
}

// --------------------------- elementwise / CG vector kernels ---------------

// r = 0, Ap = 0, x = volume (single pass)
__global__ void k_init(const float* __restrict__ volume) {
    float4* r4  = (float4*)g_r;
    float4* a4  = (float4*)g_Ap;
    float4* x4  = (float4*)g_x;
    const float4* v4 = (const float4*)volume;
    float4 z = make_float4(0.f, 0.f, 0.f, 0.f);
    for (int i = blockIdx.x * TPB + threadIdx.x; i < NVOX/4; i += TPB * NBLK) {
        r4[i] = z;
        a4[i] = z;
        x4[i] = v4[i];
    }
}

__global__ void k_relu(float* __restrict__ out) {
    float4* o4 = (float4*)out;
    const float4* x4 = (const float4*)g_x;
    for (int i = blockIdx.x * TPB + threadIdx.x; i < NVOX/4; i += TPB * NBLK) {
        float4 v = x4[i];
        o4[i] = make_float4(fmaxf(v.x, 0.f), fmaxf(v.y, 0.f),
                            fmaxf(v.z, 0.f), fmaxf(v.w, 0.f));
    }
}

// p = r; rr partials -> g_part_rr[0]
__global__ void k_initp() {
    double s = 0.0;
    const float4* r4 = (const float4*)g_r;
    float4* p4 = (float4*)g_p;
    for (int i = blockIdx.x * TPB + threadIdx.x; i < NVOX/4; i += TPB * NBLK) {
        float4 rv = r4[i];
        p4[i] = rv;
        s += (double)rv.x*rv.x + (double)rv.y*rv.y + (double)rv.z*rv.z + (double)rv.w*rv.w;
    }
    block_reduce_store(s, g_part_rr[0]);
}

// Finalize alpha = rr_old/pAp per block (redundant, deterministic), then
// x += alpha p; r -= alpha Ap; rr_new partials -> g_part_rr[cur^1].
__global__ void k_update_xr(int cur) {
    int t = threadIdx.x;
    double rr_l = g_part_rr[cur][t] + g_part_rr[cur][t + 256]
                + g_part_rr[cur][t + 512] + g_part_rr[cur][t + 768];
    double pp_l = g_part_pAp[t] + g_part_pAp[t + 256]
                + g_part_pAp[t + 512] + g_part_pAp[t + 768];
    double rr_old, pAp;
    block_reduce2_all(rr_l, pp_l, rr_old, pAp);
    float alpha = (float)(rr_old / pAp);

    double s = 0.0;
    float4* x4 = (float4*)g_x;
    float4* r4 = (float4*)g_r;
    const float4* p4 = (const float4*)g_p;
    const float4* a4 = (const float4*)g_Ap;
    for (int i = blockIdx.x * TPB + t; i < NVOX/4; i += TPB * NBLK) {
        float4 xv = x4[i], rv = r4[i], pv = p4[i], av = a4[i];
        xv.x += alpha * pv.x; xv.y += alpha * pv.y;
        xv.z += alpha * pv.z; xv.w += alpha * pv.w;
        rv.x -= alpha * av.x; rv.y -= alpha * av.y;
        rv.z -= alpha * av.z; rv.w -= alpha * av.w;
        x4[i] = xv; r4[i] = rv;
        s += (double)rv.x*rv.x + (double)rv.y*rv.y + (double)rv.z*rv.z + (double)rv.w*rv.w;
    }
    block_reduce_store(s, g_part_rr[cur ^ 1]);
}

// Finalize beta = rr_new/rr_old per block, then p = r + beta p; Ap = 0.
__global__ void k_update_p(int cur) {
    int t = threadIdx.x;
    int nxt = cur ^ 1;
    double rrn_l = g_part_rr[nxt][t] + g_part_rr[nxt][t + 256]
                 + g_part_rr[nxt][t + 512] + g_part_rr[nxt][t + 768];
    double rro_l = g_part_rr[cur][t] + g_part_rr[cur][t + 256]
                 + g_part_rr[cur][t + 512] + g_part_rr[cur][t + 768];
    double rr_new, rr_old;
    block_reduce2_all(rrn_l, rro_l, rr_new, rr_old);
    float beta = (float)(rr_new / rr_old);

    float4* p4 = (float4*)g_p;
    float4* a4 = (float4*)g_Ap;
    const float4* r4 = (const float4*)g_r;
    float4 z = make_float4(0.f, 0.f, 0.f, 0.f);
    for (int i = blockIdx.x * TPB + t; i < NVOX/4; i += TPB * NBLK) {
        float4 rv = r4[i], pv = p4[i];
        pv.x = rv.x + beta * pv.x; pv.y = rv.y + beta * pv.y;
        pv.z = rv.z + beta * pv.z; pv.w = rv.w + beta * pv.w;
        p4[i] = pv;
        a4[i] = z;
    }
}

// --------------------------- driver ----------------------------------------

extern "C" void kernel_launch(void* const* d_in, const int* in_sizes, int n_in,
                              void* d_out, int out_size) {
    const float* theta  = (const float*)d_in[0];
    const float* slices = (const float*)d_in[1];
    const float* volume = (const float*)d_in[2];
    const float* psf    = (const float*)d_in[3];
    float* out = (float*)d_out;
    (void)in_sizes; (void)n_in; (void)out_size;

    // r = At(slices) - AtA(x);  x = volume;  p = r; rr partials
    k_init<<<NBLK, TPB>>>(volume);
    k_At_slices<<<PIX_BLOCKS, TPB>>>(theta, psf, slices);
    k_AtA<<<PIX_BLOCKS, TPB>>>(theta, psf, 0, 1, -1.f, 0);
    k_initp<<<NBLK, TPB>>>();

    int cur = 0;
    for (int it = 0; it < 10; it++) {
        // Ap = AtA(p); pAp partials fused
        k_AtA<<<PIX_BLOCKS, TPB>>>(theta, psf, 1, 2, 1.f, 1);
        // x,r update (finalizes alpha in-block) + rr_new partials
        k_update_xr<<<NBLK, TPB>>>(cur);
        // p update (finalizes beta in-block) + zero Ap
        k_update_p<<<NBLK, TPB>>>(cur);
        cur ^= 1;
    }

    k_relu<<<NBLK, TPB>>>(out);
}

// round 15
// speedup vs baseline: 2.1219x; 2.1219x over previous
#include <cuda_runtime.h>

// ---------------------------------------------------------------------------
// SRR CG: out = relu(CG(AtA, b=At(slices), x0=volume, 10 iters))
// R12 = R9 VERBATIM (control run). R10/R11 regressed 2x with changes whose
// honest cost model is <100us; the one comparable streaming kernel showed a
// 3x bandwidth drop across sessions -> suspected degraded container state.
// Re-establishing the 1087us baseline before further edits.
// ---------------------------------------------------------------------------

#define NVOX (128*128*128)
#define NPIX (16*128*128)
#define TPB 256
#define NBLK 1024
#define PIX_BLOCKS (NPIX / TPB)

__device__ float g_b[NVOX];
__device__ float g_x[NVOX];
__device__ float g_r[NVOX];
__device__ float g_p[NVOX];
__device__ float g_Ap[NVOX];
__device__ double g_scal[3];            // [0],[1]: rr ping-pong, [2]: pAp
__device__ double g_partial[NBLK];

// --------------------------- per-pixel frame -------------------------------

struct Frame {
    float R[9];
    float cx, cy, cz;
};

__device__ __forceinline__ Frame make_frame(int idx, const float* __restrict__ theta) {
    int w = idx & 127;
    int h = (idx >> 7) & 127;
    int n = idx >> 14;
    const float* T = theta + n * 12;
    Frame f;
    f.R[0] = T[0];  f.R[1] = T[1];  f.R[2] = T[2];
    f.R[3] = T[4];  f.R[4] = T[5];  f.R[5] = T[6];
    f.R[6] = T[8];  f.R[7] = T[9];  f.R[8] = T[10];
    float u = ((float)w - 63.5f) * 1.5f;
    float v = ((float)h - 63.5f) * 1.5f;
    f.cx = f.R[0]*u + f.R[1]*v + T[3]  + 63.5f;
    f.cy = f.R[3]*u + f.R[4]*v + T[7]  + 63.5f;
    f.cz = f.R[6]*u + f.R[7]*v + T[11] + 63.5f;
    return f;
}

// Center further than (sqrt(3) rotated PSF offset + 1 trilinear corner)
// outside [0,127] in any axis -> whole footprint out of bounds -> zero.
__device__ __forceinline__ bool in_range(const Frame& f) {
    return f.cx > -2.75f && f.cx < 129.75f &&
           f.cy > -2.75f && f.cy < 129.75f &&
           f.cz > -2.75f && f.cz < 129.75f;
}

__device__ __forceinline__ void block_reduce_store(double s) {
    __shared__ double sm[TPB];
    sm[threadIdx.x] = s;
    __syncthreads();
    for (int off = TPB / 2; off > 0; off >>= 1) {
        if (threadIdx.x < off) sm[threadIdx.x] += sm[threadIdx.x + off];
        __syncthreads();
    }
    if (threadIdx.x == 0) g_partial[blockIdx.x] = sm[0];
}

// --------------------------- gather / scatter cores ------------------------

__device__ __forceinline__ float gather27(const Frame& f,
                                          const float* __restrict__ vol,
                                          const float* __restrict__ psf) {
    float acc = 0.f;
    int k = 0;
    #pragma unroll
    for (int a = -1; a <= 1; a++) {
        float oz = (float)a;
        #pragma unroll
        for (int b = -1; b <= 1; b++) {
            float oy = (float)b;
            #pragma unroll
            for (int c = -1; c <= 1; c++, k++) {
                float ox = (float)c;
                float px = f.cx + f.R[0]*ox + f.R[1]*oy + f.R[2]*oz;
                float py = f.cy + f.R[3]*ox + f.R[4]*oy + f.R[5]*oz;
                float pz = f.cz + f.R[6]*ox + f.R[7]*oy + f.R[8]*oz;
                float pk = __ldg(&psf[k]);
                float xf = floorf(px), yf = floorf(py), zf = floorf(pz);
                int x0 = (int)xf, y0 = (int)yf, z0 = (int)zf;
                float fx = px - xf, fy = py - yf, fz = pz - zf;
                float wx0 = 1.f - fx, wy0 = 1.f - fy, wz0 = 1.f - fz;
                float s = 0.f;
                #pragma unroll
                for (int dz = 0; dz < 2; dz++) {
                    float wz = dz ? fz : wz0;
                    int zi = z0 + dz;
                    #pragma unroll
                    for (int dy = 0; dy < 2; dy++) {
                        float wy = dy ? fy : wy0;
                        int yi = y0 + dy;
                        #pragma unroll
                        for (int dx = 0; dx < 2; dx++) {
                            float wx = dx ? fx : wx0;
                            int xi = x0 + dx;
                            if ((unsigned)xi < 128u && (unsigned)yi < 128u && (unsigned)zi < 128u)
                                s += wx * wy * wz * __ldg(&vol[(zi * 128 + yi) * 128 + xi]);
                        }
                    }
                }
                acc += pk * s;
            }
        }
    }
    return acc;
}

__device__ __forceinline__ void scatter27(const Frame& f, float* __restrict__ vol,
                                          const float* __restrict__ psf, float val) {
    int k = 0;
    #pragma unroll
    for (int a = -1; a <= 1; a++) {
        float oz = (float)a;
        #pragma unroll
        for (int b = -1; b <= 1; b++) {
            float oy = (float)b;
            #pragma unroll
            for (int c = -1; c <= 1; c++, k++) {
                float ox = (float)c;
                float px = f.cx + f.R[0]*ox + f.R[1]*oy + f.R[2]*oz;
                float py = f.cy + f.R[3]*ox + f.R[4]*oy + f.R[5]*oz;
                float pz = f.cz + f.R[6]*ox + f.R[7]*oy + f.R[8]*oz;
                float base = val * __ldg(&psf[k]);
                float xf = floorf(px), yf = floorf(py), zf = floorf(pz);
                int x0 = (int)xf, y0 = (int)yf, z0 = (int)zf;
                float fx = px - xf, fy = py - yf, fz = pz - zf;
                float wx0 = 1.f - fx, wy0 = 1.f - fy, wz0 = 1.f - fz;
                #pragma unroll
                for (int dz = 0; dz < 2; dz++) {
                    int zi = z0 + dz;
                    if ((unsigned)zi >= 128u) continue;
                    float bz = base * (dz ? fz : wz0);
                    #pragma unroll
                    for (int dy = 0; dy < 2; dy++) {
                        int yi = y0 + dy;
                        if ((unsigned)yi >= 128u) continue;
                        float byz = bz * (dy ? fy : wy0);
                        float* row = vol + (zi * 128 + yi) * 128;
                        if ((unsigned)x0 < 128u)       atomicAdd(row + x0,     byz * wx0);
                        if ((unsigned)(x0 + 1) < 128u) atomicAdd(row + x0 + 1, byz * fx);
                    }
                }
            }
        }
    }
}

// --------------------------- fused AtA kernel ------------------------------
// src_sel: 0 -> g_x, 1 -> g_p.   dst_sel: 1 -> g_r, 2 -> g_Ap.
// Per pixel: a = <w, src>;  dst += sign * a * w;  optional pAp partials (a^2).

__global__ void k_AtA(const float* __restrict__ theta, const float* __restrict__ psf,
                      int src_sel, int dst_sel, float sign, int do_dot) {
    const float* __restrict__ src = src_sel == 0 ? g_x : g_p;
    float* __restrict__ dst = dst_sel == 1 ? g_r : g_Ap;
    int idx = blockIdx.x * TPB + threadIdx.x;
    Frame f = make_frame(idx, theta);
    float acc = 0.f;
    bool inr = in_range(f);
    if (inr)
        acc = gather27(f, src, psf);
    if (do_dot)
        block_reduce_store((double)acc * (double)acc);
    float val = sign * acc;
    if (inr && val != 0.f)
        scatter27(f, dst, psf, val);
}

// --------------------------- At (slices -> b) ------------------------------

__global__ void k_At_slices(const float* __restrict__ theta, const float* __restrict__ psf,
                            const float* __restrict__ slices) {
    int idx = blockIdx.x * TPB + threadIdx.x;
    Frame f = make_frame(idx, theta);
    if (!in_range(f)) return;
    float val = slices[idx];
    if (val == 0.f) return;
    scatter27(f, g_b, psf, val);
}

// --------------------------- elementwise / reductions ----------------------

// b = 0, Ap = 0, x = volume (single pass)
__global__ void k_init(const float* __restrict__ volume) {
    float4* b4  = (float4*)g_b;
    float4* a4  = (float4*)g_Ap;
    float4* x4  = (float4*)g_x;
    const float4* v4 = (const float4*)volume;
    float4 z = make_float4(0.f, 0.f, 0.f, 0.f);
    for (int i = blockIdx.x * TPB + threadIdx.x; i < NVOX/4; i += TPB * NBLK) {
        b4[i] = z;
        a4[i] = z;
        x4[i] = v4[i];
    }
}

__global__ void k_r_from_b() {
    float4* r4 = (float4*)g_r;
    const float4* b4 = (const float4*)g_b;
    for (int i = blockIdx.x * TPB + threadIdx.x; i < NVOX/4; i += TPB * NBLK)
        r4[i] = b4[i];
}

__global__ void k_relu(float* __restrict__ out) {
    float4* o4 = (float4*)out;
    const float4* x4 = (const float4*)g_x;
    for (int i = blockIdx.x * TPB + threadIdx.x; i < NVOX/4; i += TPB * NBLK) {
        float4 v = x4[i];
        o4[i] = make_float4(fmaxf(v.x, 0.f), fmaxf(v.y, 0.f),
                            fmaxf(v.z, 0.f), fmaxf(v.w, 0.f));
    }
}

__global__ void k_fin(int slot) {
    __shared__ double sm[TPB];
    double s = 0.0;
    for (int i = threadIdx.x; i < NBLK; i += TPB) s += g_partial[i];
    sm[threadIdx.x] = s;
    __syncthreads();
    for (int off = TPB / 2; off > 0; off >>= 1) {
        if (threadIdx.x < off) sm[threadIdx.x] += sm[threadIdx.x + off];
        __syncthreads();
    }
    if (threadIdx.x == 0) g_scal[slot] = sm[0];
}

// p = r, plus partials of r.r
__global__ void k_initp() {
    double s = 0.0;
    const float4* r4 = (const float4*)g_r;
    float4* p4 = (float4*)g_p;
    for (int i = blockIdx.x * TPB + threadIdx.x; i < NVOX/4; i += TPB * NBLK) {
        float4 rv = r4[i];
        p4[i] = rv;
        s += (double)rv.x*rv.x + (double)rv.y*rv.y + (double)rv.z*rv.z + (double)rv.w*rv.w;
    }
    block_reduce_store(s);
}

// alpha = rr/pAp;  x += alpha p;  r -= alpha Ap;  partials of new r.r
__global__ void k_update_xr(int rr_slot) {
    float alpha = (float)(g_scal[rr_slot] / g_scal[2]);
    double s = 0.0;
    float4* x4 = (float4*)g_x;
    float4* r4 = (float4*)g_r;
    const float4* p4 = (const float4*)g_p;
    const float4* a4 = (const float4*)g_Ap;
    for (int i = blockIdx.x * TPB + threadIdx.x; i < NVOX/4; i += TPB * NBLK) {
        float4 xv = x4[i], rv = r4[i], pv = p4[i], av = a4[i];
        xv.x += alpha * pv.x; xv.y += alpha * pv.y;
        xv.z += alpha * pv.z; xv.w += alpha * pv.w;
        rv.x -= alpha * av.x; rv.y -= alpha * av.y;
        rv.z -= alpha * av.z; rv.w -= alpha * av.w;
        x4[i] = xv; r4[i] = rv;
        s += (double)rv.x*rv.x + (double)rv.y*rv.y + (double)rv.z*rv.z + (double)rv.w*rv.w;
    }
    block_reduce_store(s);
}

// beta = rr_new/rr_old;  p = r + beta p;  Ap = 0 (ready for next iteration)
__global__ void k_update_p(int cur, int nxt) {
    float beta = (float)(g_scal[nxt] / g_scal[cur]);
    float4* p4 = (float4*)g_p;
    float4* a4 = (float4*)g_Ap;
    const float4* r4 = (const float4*)g_r;
    float4 z = make_float4(0.f, 0.f, 0.f, 0.f);
    for (int i = blockIdx.x * TPB + threadIdx.x; i < NVOX/4; i += TPB * NBLK) {
        float4 rv = r4[i], pv = p4[i];
        pv.x = rv.x + beta * pv.x; pv.y = rv.y + beta * pv.y;
        pv.z = rv.z + beta * pv.z; pv.w = rv.w + beta * pv.w;
        p4[i] = pv;
        a4[i] = z;
    }
}

// --------------------------- driver ----------------------------------------

extern "C" void kernel_launch(void* const* d_in, const int* in_sizes, int n_in,
                              void* d_out, int out_size) {
    const float* theta  = (const float*)d_in[0];
    const float* slices = (const float*)d_in[1];
    const float* volume = (const float*)d_in[2];
    const float* psf    = (const float*)d_in[3];
    float* out = (float*)d_out;
    (void)in_sizes; (void)n_in; (void)out_size;

    // init: b=0, Ap=0, x=volume;  b = At(slices)
    k_init<<<NBLK, TPB>>>(volume);
    k_At_slices<<<PIX_BLOCKS, TPB>>>(theta, psf, slices);

    // r = b; r -= AtA(x)  (fused); p = r; rr = dot(r,r)
    k_r_from_b<<<NBLK, TPB>>>();
    k_AtA<<<PIX_BLOCKS, TPB>>>(theta, psf, 0, 1, -1.f, 0);
    k_initp<<<NBLK, TPB>>>();
    k_fin<<<1, TPB>>>(0);

    int cur = 0;
    for (int it = 0; it < 10; it++) {
        int nxt = cur ^ 1;
        // Ap = AtA(p), pAp partials fused
        k_AtA<<<PIX_BLOCKS, TPB>>>(theta, psf, 1, 2, 1.f, 1);
        k_fin<<<1, TPB>>>(2);
        // x,r update + rr_new partials
        k_update_xr<<<NBLK, TPB>>>(cur);
        k_fin<<<1, TPB>>>(nxt);
        // p update + zero Ap for next iter
        k_update_p<<<NBLK, TPB>>>(cur, nxt);
        cur = nxt;
    }

    k_relu<<<NBLK, TPB>>>(out);
}